// round 6
// baseline (speedup 1.0000x reference)
#include <cuda_runtime.h>
#include <cuda_bf16.h>
#include <cuda_fp16.h>

// SoftRankNDCGLoss: B=128, L=1024
//
// s_i = f(p_i), f(x) = sum_j erf((x - p_j)/2)  (Gaussian-smoothed ECDF).
// Build f on an adaptive M=64 grid per row (tanh-cubic erf approx evaluated
// with tanh.approx.f16x2 — one MUFU per TWO evals), cubic-interpolate f(p_i).
// er_i = 512.5 + 0.5*f(p_i); dcg = sum (2^t-1)/log2(er+1); idcg via counting
// sort; out = -mean_b(dcg/(idcg+1e-10)), fused last-block finalize.

constexpr int BATCH = 128;
constexpr int LEN   = 1024;
constexpr int M     = 64;               // grid points per row
constexpr int SUBS  = LEN / M;          // 16 j-chunks
constexpr int TPB   = 1024;

__device__ float g_ndcg[BATCH];
__device__ int   g_done = 0;

typedef unsigned long long ull;

__device__ __forceinline__ ull pack2(float lo, float hi) {
    ull r; asm("mov.b64 %0, {%1, %2};" : "=l"(r) : "f"(lo), "f"(hi)); return r;
}
__device__ __forceinline__ void unpack2(ull v, float& lo, float& hi) {
    asm("mov.b64 {%0, %1}, %2;" : "=f"(lo), "=f"(hi) : "l"(v));
}
__device__ __forceinline__ ull add2(ull a, ull b) {
    ull r; asm("add.rn.f32x2 %0, %1, %2;" : "=l"(r) : "l"(a), "l"(b)); return r;
}
__device__ __forceinline__ ull mul2(ull a, ull b) {
    ull r; asm("mul.rn.f32x2 %0, %1, %2;" : "=l"(r) : "l"(a), "l"(b)); return r;
}
__device__ __forceinline__ ull fma2(ull a, ull b, ull c) {
    ull r; asm("fma.rn.f32x2 %0, %1, %2, %3;" : "=l"(r) : "l"(a), "l"(b), "l"(c)); return r;
}
// pack two f32 into f16x2 (hi <- first operand, lo <- second)
__device__ __forceinline__ unsigned cvt_h2(float hi, float lo) {
    unsigned r; asm("cvt.rn.f16x2.f32 %0, %1, %2;" : "=r"(r) : "f"(hi), "f"(lo)); return r;
}
__device__ __forceinline__ unsigned tanh_h2(unsigned x) {
    unsigned r; asm("tanh.approx.f16x2 %0, %1;" : "=r"(r) : "r"(x)); return r;
}
__device__ __forceinline__ unsigned hadd2(unsigned a, unsigned b) {
    unsigned r; asm("add.rn.f16x2 %0, %1, %2;" : "=r"(r) : "r"(a), "r"(b)); return r;
}
__device__ __forceinline__ float h2_sum_f32(unsigned v) {
    __half2 h = *reinterpret_cast<__half2*>(&v);
    return __low2float(h) + __high2float(h);
}
// integer warp redux (supported on sm_103; f32 redux is NOT)
__device__ __forceinline__ unsigned redux_min_u32(unsigned v) {
    unsigned r; asm("redux.sync.min.u32 %0, %1, 0xffffffff;" : "=r"(r) : "r"(v)); return r;
}
__device__ __forceinline__ unsigned redux_max_u32(unsigned v) {
    unsigned r; asm("redux.sync.max.u32 %0, %1, 0xffffffff;" : "=r"(r) : "r"(v)); return r;
}
// monotone float <-> u32 key
__device__ __forceinline__ unsigned f2key(float f) {
    unsigned b = __float_as_uint(f);
    return (b & 0x80000000u) ? ~b : (b | 0x80000000u);
}
__device__ __forceinline__ float key2f(unsigned k) {
    unsigned b = (k & 0x80000000u) ? (k & 0x7FFFFFFFu) : ~k;
    return __uint_as_float(b);
}
__device__ __forceinline__ float warp_sum(float v) {
    #pragma unroll
    for (int o = 16; o > 0; o >>= 1)
        v += __shfl_down_sync(0xFFFFFFFFu, v, o);
    return v;
}

__global__ __launch_bounds__(TPB, 1) void ndcg_kernel(
    const float* __restrict__ preds,
    const float* __restrict__ target,
    float* __restrict__ out)
{
    __shared__ __align__(16) float sn[LEN];        // negated preds row
    __shared__ float spart[SUBS][M];               // grid partials
    __shared__ float sg[M];                        // grid f values
    __shared__ float sred[64];
    __shared__ unsigned skey[64];                  // min/max keys
    __shared__ float s_lo, s_hi;
    __shared__ int   scnt[5];
    __shared__ int   slast;

    const int b    = blockIdx.x;
    const int tid  = threadIdx.x;
    const int lane = tid & 31;
    const int warp = tid >> 5;

    const float pi = preds[b * LEN + tid];
    const float ti = target[b * LEN + tid];
    sn[tid] = -pi;
    if (tid < 5) scnt[tid] = 0;
    if (tid == 0) slast = 0;

    // ---- row min/max via integer redux on monotone keys ----
    const unsigned key = f2key(pi);
    const unsigned wmn = redux_min_u32(key);
    const unsigned wmx = redux_max_u32(key);
    if (lane == 0) { skey[warp] = wmn; skey[32 + warp] = wmx; }
    __syncthreads();   // sn staged, scnt zeroed, keys in skey

    // ---- grade counting via warp ballots (grade 0 count unused) ----
    const int gi = (int)ti;
    #pragma unroll
    for (int gr = 1; gr < 5; ++gr) {
        unsigned bl = __ballot_sync(0xFFFFFFFFu, gi == gr);
        if (lane == 0) atomicAdd(&scnt[gr], __popc(bl));
    }
    if (warp == 0) {
        const unsigned a = redux_min_u32(skey[lane]);
        const unsigned c = redux_max_u32(skey[32 + lane]);
        if (lane == 0) { s_lo = key2f(a); s_hi = key2f(c); }
    }
    __syncthreads();

    const float lo   = s_lo;
    const float span = fmaxf(s_hi - lo, 1e-3f);
    const float h    = span / (float)(M - 4);
    const float invh = (float)(M - 4) / span;

    // ---- build f on the grid: point m_pt, j-chunk sub ----
    const int m_pt = tid & (M - 1);
    const int sub  = tid >> 6;                     // 0..15
    const float x  = lo + ((float)m_pt - 1.5f) * h;

    const float A = 0.5641896f;
    const float B = 0.0126140f;
    const ull x2 = pack2(x, x);
    const ull A2 = pack2(A, A);
    const ull B2 = pack2(B, B);
    const ull* sn2 = reinterpret_cast<const ull*>(sn);

    // 4 rotating f16x2 accumulators: each sums only 8 tanh values per half,
    // bounding fp16 rounding error.
    unsigned acc0 = 0u, acc1 = 0u, acc2 = 0u, acc3 = 0u;
    const int base = sub * (M / 2);                // 32 x f32x2 = 64 elems
    #pragma unroll
    for (int jj = 0; jj < M / 2; jj += 4) {
        #pragma unroll
        for (int q = 0; q < 4; ++q) {
            ull v  = sn2[base + jj + q];           // LDS.64 broadcast
            ull d  = add2(x2, v);                  // x - p_j (pairwise)
            ull dd = mul2(d, d);
            ull u  = fma2(dd, B2, A2);
            ull t  = mul2(d, u);
            float t0, t1; unpack2(t, t0, t1);
            unsigned th = tanh_h2(cvt_h2(t1, t0));
            if (q == 0) acc0 = hadd2(acc0, th);
            else if (q == 1) acc1 = hadd2(acc1, th);
            else if (q == 2) acc2 = hadd2(acc2, th);
            else acc3 = hadd2(acc3, th);
        }
    }
    spart[sub][m_pt] = (h2_sum_f32(acc0) + h2_sum_f32(acc1))
                     + (h2_sum_f32(acc2) + h2_sum_f32(acc3));
    __syncthreads();

    if (tid < M) {
        float g = spart[0][tid];
        #pragma unroll
        for (int s = 1; s < SUBS; ++s) g += spart[s][tid];
        sg[tid] = g;
    }
    __syncthreads();

    // ---- cubic Lagrange interpolation of f at p_i ----
    const float u  = (pi - lo) * invh + 1.5f;
    int m = (int)floorf(u);
    m = min(max(m, 1), M - 3);
    const float tf = u - (float)m;
    const float ta = tf - 1.0f;
    const float tb = tf - 2.0f;
    const float tc = tf + 1.0f;
    const float wm1 = -tf * ta * tb * (1.0f / 6.0f);
    const float w0  =  tc * ta * tb * 0.5f;
    const float w1  = -tc * tf * tb * 0.5f;
    const float w2  =  tc * tf * ta * (1.0f / 6.0f);
    const float f = wm1 * sg[m - 1] + w0 * sg[m] + w1 * sg[m + 1] + w2 * sg[m + 2];

    const float er   = 512.5f + 0.5f * f;          // 1 + (L-1)/2 + 0.5*f
    const float gain = (float)((1 << gi) - 1);     // grades are integer 0..4
    float dcg_i = __fdividef(gain, __log2f(er + 1.0f));

    // ---- ideal DCG term at descending rank tid ----
    const int c4 = scnt[4];
    const int c3 = c4 + scnt[3];
    const int c2 = c3 + scnt[2];
    const int c1 = c2 + scnt[1];
    const int gr = (tid < c4) ? 4 : (tid < c3) ? 3 : (tid < c2) ? 2 : (tid < c1) ? 1 : 0;
    float idcg_i = __fdividef((float)((1 << gr) - 1), __log2f((float)(tid + 2)));

    // ---- block reduction (dcg, idcg together) ----
    #pragma unroll
    for (int o = 16; o > 0; o >>= 1) {
        dcg_i  += __shfl_down_sync(0xFFFFFFFFu, dcg_i,  o);
        idcg_i += __shfl_down_sync(0xFFFFFFFFu, idcg_i, o);
    }
    __syncthreads();   // sred reuse safe
    if (lane == 0) { sred[warp] = dcg_i; sred[32 + warp] = idcg_i; }
    __syncthreads();

    if (warp == 0) {
        float d  = sred[lane];
        float id = sred[32 + lane];
        #pragma unroll
        for (int o = 16; o > 0; o >>= 1) {
            d  += __shfl_down_sync(0xFFFFFFFFu, d,  o);
            id += __shfl_down_sync(0xFFFFFFFFu, id, o);
        }
        if (lane == 0) {
            g_ndcg[b] = d / (id + 1e-10f);
            __threadfence();
            int old = atomicAdd(&g_done, 1);
            slast = (old == gridDim.x - 1);
        }
    }
    __syncthreads();

    // ---- fused finalize: last CTA computes the mean ----
    if (slast) {
        if (tid < BATCH) {
            float v = warp_sum(g_ndcg[tid]);
            if (lane == 0) sred[warp] = v;
        }
        __syncthreads();
        if (tid == 0) {
            float s = sred[0] + sred[1] + sred[2] + sred[3];
            out[0] = -s / (float)BATCH;
            g_done = 0;                 // reset for next graph replay
        }
    }
}

extern "C" void kernel_launch(void* const* d_in, const int* in_sizes, int n_in,
                              void* d_out, int out_size)
{
    const float* preds  = (const float*)d_in[0];
    const float* target = (const float*)d_in[1];
    float* out = (float*)d_out;

    ndcg_kernel<<<BATCH, TPB>>>(preds, target, out);
}

// round 7
// speedup vs baseline: 1.2250x; 1.2250x over previous
#include <cuda_runtime.h>
#include <cuda_bf16.h>

// SoftRankNDCGLoss: B=128, L=1024
//
// s_i = f(p_i), f(x) = sum_j erf((x - p_j)/2)  (Gaussian-smoothed ECDF).
// Build f on an adaptive M=32 grid per row (tanh-cubic erf approx, HW tanh,
// packed f32x2), cubic-interpolate f at each p_i.
// er_i = 512.5 + 0.5*f(p_i); dcg = sum (2^t-1)/log2(er+1); idcg via counting
// sort; out = -mean_b(dcg/(idcg+1e-10)), fused last-block finalize.

constexpr int BATCH = 128;
constexpr int LEN   = 1024;
constexpr int M     = 32;               // grid points per row
constexpr int SUBS  = LEN / M;          // 32 j-chunks (one per warp)
constexpr int TPB   = 1024;

__device__ float g_ndcg[BATCH];
__device__ int   g_done = 0;

typedef unsigned long long ull;

__device__ __forceinline__ ull pack2(float lo, float hi) {
    ull r; asm("mov.b64 %0, {%1, %2};" : "=l"(r) : "f"(lo), "f"(hi)); return r;
}
__device__ __forceinline__ void unpack2(ull v, float& lo, float& hi) {
    asm("mov.b64 {%0, %1}, %2;" : "=f"(lo), "=f"(hi) : "l"(v));
}
__device__ __forceinline__ ull add2(ull a, ull b) {
    ull r; asm("add.rn.f32x2 %0, %1, %2;" : "=l"(r) : "l"(a), "l"(b)); return r;
}
__device__ __forceinline__ ull mul2(ull a, ull b) {
    ull r; asm("mul.rn.f32x2 %0, %1, %2;" : "=l"(r) : "l"(a), "l"(b)); return r;
}
__device__ __forceinline__ ull fma2(ull a, ull b, ull c) {
    ull r; asm("fma.rn.f32x2 %0, %1, %2, %3;" : "=l"(r) : "l"(a), "l"(b), "l"(c)); return r;
}
__device__ __forceinline__ float tanh_fast(float x) {
    float r; asm("tanh.approx.f32 %0, %1;" : "=f"(r) : "f"(x)); return r;
}
// integer warp redux (supported on sm_103; f32 redux is NOT)
__device__ __forceinline__ unsigned redux_min_u32(unsigned v) {
    unsigned r; asm("redux.sync.min.u32 %0, %1, 0xffffffff;" : "=r"(r) : "r"(v)); return r;
}
__device__ __forceinline__ unsigned redux_max_u32(unsigned v) {
    unsigned r; asm("redux.sync.max.u32 %0, %1, 0xffffffff;" : "=r"(r) : "r"(v)); return r;
}
// monotone float <-> u32 key
__device__ __forceinline__ unsigned f2key(float f) {
    unsigned b = __float_as_uint(f);
    return (b & 0x80000000u) ? ~b : (b | 0x80000000u);
}
__device__ __forceinline__ float key2f(unsigned k) {
    unsigned b = (k & 0x80000000u) ? (k & 0x7FFFFFFFu) : ~k;
    return __uint_as_float(b);
}
__device__ __forceinline__ float warp_sum(float v) {
    #pragma unroll
    for (int o = 16; o > 0; o >>= 1)
        v += __shfl_down_sync(0xFFFFFFFFu, v, o);
    return v;
}

__global__ __launch_bounds__(TPB, 1) void ndcg_kernel(
    const float* __restrict__ preds,
    const float* __restrict__ target,
    float* __restrict__ out)
{
    __shared__ __align__(16) float sn[LEN];        // negated preds row
    __shared__ float spart[SUBS][M];               // grid partials
    __shared__ float sg[M];                        // grid f values
    __shared__ float sred[64];
    __shared__ unsigned skey[64];                  // min/max keys
    __shared__ float s_lo, s_hi;
    __shared__ int   scnt[5];
    __shared__ int   slast;

    const int b    = blockIdx.x;
    const int tid  = threadIdx.x;
    const int lane = tid & 31;
    const int warp = tid >> 5;

    const float pi = preds[b * LEN + tid];
    const float ti = target[b * LEN + tid];
    sn[tid] = -pi;
    if (tid < 5) scnt[tid] = 0;
    if (tid == 0) slast = 0;

    // ---- row min/max via integer redux on monotone keys ----
    const unsigned key = f2key(pi);
    const unsigned wmn = redux_min_u32(key);
    const unsigned wmx = redux_max_u32(key);
    if (lane == 0) { skey[warp] = wmn; skey[32 + warp] = wmx; }
    __syncthreads();   // sn staged, scnt zeroed, keys in skey

    // ---- grade counting via warp ballots (grade 0 count unused) ----
    const int gi = (int)ti;
    #pragma unroll
    for (int gr = 1; gr < 5; ++gr) {
        unsigned bl = __ballot_sync(0xFFFFFFFFu, gi == gr);
        if (lane == 0) atomicAdd(&scnt[gr], __popc(bl));
    }
    if (warp == 0) {
        const unsigned a = redux_min_u32(skey[lane]);
        const unsigned c = redux_max_u32(skey[32 + lane]);
        if (lane == 0) { s_lo = key2f(a); s_hi = key2f(c); }
    }
    __syncthreads();

    const float lo   = s_lo;
    const float span = fmaxf(s_hi - lo, 1e-3f);
    const float h    = span / (float)(M - 4);
    const float invh = (float)(M - 4) / span;

    // ---- build f on the grid: point = lane, j-chunk = warp ----
    const int m_pt = lane;
    const int sub  = warp;                         // 0..31
    const float x  = lo + ((float)m_pt - 1.5f) * h;

    const float A = 0.5641896f;
    const float B = 0.0126140f;
    const ull x2 = pack2(x, x);
    const ull A2 = pack2(A, A);
    const ull B2 = pack2(B, B);
    const ull* sn2 = reinterpret_cast<const ull*>(sn);

    float s0 = 0.0f, s1 = 0.0f;
    const int base = sub * (M / 2);                // 16 x f32x2 = 32 elems
    #pragma unroll
    for (int jj = 0; jj < M / 2; ++jj) {
        ull v  = sn2[base + jj];                   // LDS.64 broadcast
        ull d  = add2(x2, v);                      // x - p_j (pairwise)
        ull dd = mul2(d, d);
        ull u  = fma2(dd, B2, A2);
        ull t  = mul2(d, u);
        float t0, t1; unpack2(t, t0, t1);
        s0 += tanh_fast(t0);
        s1 += tanh_fast(t1);
    }
    spart[sub][m_pt] = s0 + s1;
    __syncthreads();

    if (tid < M) {
        float g = spart[0][tid];
        #pragma unroll
        for (int s = 1; s < SUBS; ++s) g += spart[s][tid];
        sg[tid] = g;
    }
    __syncthreads();

    // ---- cubic Lagrange interpolation of f at p_i ----
    const float u  = (pi - lo) * invh + 1.5f;
    int m = (int)floorf(u);
    m = min(max(m, 1), M - 3);
    const float tf = u - (float)m;
    const float ta = tf - 1.0f;
    const float tb = tf - 2.0f;
    const float tc = tf + 1.0f;
    const float wm1 = -tf * ta * tb * (1.0f / 6.0f);
    const float w0  =  tc * ta * tb * 0.5f;
    const float w1  = -tc * tf * tb * 0.5f;
    const float w2  =  tc * tf * ta * (1.0f / 6.0f);
    const float f = wm1 * sg[m - 1] + w0 * sg[m] + w1 * sg[m + 1] + w2 * sg[m + 2];

    const float er   = 512.5f + 0.5f * f;          // 1 + (L-1)/2 + 0.5*f
    const float gain = (float)((1 << gi) - 1);     // grades are integer 0..4
    float dcg_i = __fdividef(gain, __log2f(er + 1.0f));

    // ---- ideal DCG term at descending rank tid ----
    const int c4 = scnt[4];
    const int c3 = c4 + scnt[3];
    const int c2 = c3 + scnt[2];
    const int c1 = c2 + scnt[1];
    const int gr = (tid < c4) ? 4 : (tid < c3) ? 3 : (tid < c2) ? 2 : (tid < c1) ? 1 : 0;
    float idcg_i = __fdividef((float)((1 << gr) - 1), __log2f((float)(tid + 2)));

    // ---- block reduction (dcg, idcg together) ----
    #pragma unroll
    for (int o = 16; o > 0; o >>= 1) {
        dcg_i  += __shfl_down_sync(0xFFFFFFFFu, dcg_i,  o);
        idcg_i += __shfl_down_sync(0xFFFFFFFFu, idcg_i, o);
    }
    __syncthreads();   // sred reuse safe
    if (lane == 0) { sred[warp] = dcg_i; sred[32 + warp] = idcg_i; }
    __syncthreads();

    if (warp == 0) {
        float d  = sred[lane];
        float id = sred[32 + lane];
        #pragma unroll
        for (int o = 16; o > 0; o >>= 1) {
            d  += __shfl_down_sync(0xFFFFFFFFu, d,  o);
            id += __shfl_down_sync(0xFFFFFFFFu, id, o);
        }
        if (lane == 0) {
            g_ndcg[b] = d / (id + 1e-10f);
            __threadfence();
            int old = atomicAdd(&g_done, 1);
            slast = (old == gridDim.x - 1);
        }
    }
    __syncthreads();

    // ---- fused finalize: last CTA computes the mean ----
    if (slast) {
        if (tid < BATCH) {
            float v = warp_sum(g_ndcg[tid]);
            if (lane == 0) sred[warp] = v;
        }
        __syncthreads();
        if (tid == 0) {
            float s = sred[0] + sred[1] + sred[2] + sred[3];
            out[0] = -s / (float)BATCH;
            g_done = 0;                 // reset for next graph replay
        }
    }
}

extern "C" void kernel_launch(void* const* d_in, const int* in_sizes, int n_in,
                              void* d_out, int out_size)
{
    const float* preds  = (const float*)d_in[0];
    const float* target = (const float*)d_in[1];
    float* out = (float*)d_out;

    ndcg_kernel<<<BATCH, TPB>>>(preds, target, out);
}

// round 8
// speedup vs baseline: 1.2610x; 1.0294x over previous
#include <cuda_runtime.h>
#include <cuda_bf16.h>

// SoftRankNDCGLoss: B=128, L=1024
//
// s_i = f(p_i), f(x) = sum_j erf((x - p_j)/2)  (Gaussian-smoothed ECDF).
// Build f on an adaptive M=16 grid per row (tanh-cubic erf approx, HW tanh,
// packed f32x2), cubic-interpolate f at each p_i.
// er_i = 512.5 + 0.5*f(p_i); dcg = sum (2^t-1)/log2(er+1); idcg via counting
// sort; out = -mean_b(dcg/(idcg+1e-10)), fused last-block finalize
// (acq_rel atomic, no threadfence).

constexpr int BATCH = 128;
constexpr int LEN   = 1024;
constexpr int M     = 16;               // grid points per row
constexpr int SUBS  = LEN / M;          // 64 j-chunks
constexpr int TPB   = 1024;

__device__ float g_ndcg[BATCH];
__device__ unsigned g_done = 0;

typedef unsigned long long ull;

__device__ __forceinline__ ull pack2(float lo, float hi) {
    ull r; asm("mov.b64 %0, {%1, %2};" : "=l"(r) : "f"(lo), "f"(hi)); return r;
}
__device__ __forceinline__ void unpack2(ull v, float& lo, float& hi) {
    asm("mov.b64 {%0, %1}, %2;" : "=f"(lo), "=f"(hi) : "l"(v));
}
__device__ __forceinline__ ull add2(ull a, ull b) {
    ull r; asm("add.rn.f32x2 %0, %1, %2;" : "=l"(r) : "l"(a), "l"(b)); return r;
}
__device__ __forceinline__ ull mul2(ull a, ull b) {
    ull r; asm("mul.rn.f32x2 %0, %1, %2;" : "=l"(r) : "l"(a), "l"(b)); return r;
}
__device__ __forceinline__ ull fma2(ull a, ull b, ull c) {
    ull r; asm("fma.rn.f32x2 %0, %1, %2, %3;" : "=l"(r) : "l"(a), "l"(b), "l"(c)); return r;
}
__device__ __forceinline__ float tanh_fast(float x) {
    float r; asm("tanh.approx.f32 %0, %1;" : "=f"(r) : "f"(x)); return r;
}
// integer warp redux (supported on sm_103; f32 redux is NOT)
__device__ __forceinline__ unsigned redux_min_u32(unsigned v) {
    unsigned r; asm("redux.sync.min.u32 %0, %1, 0xffffffff;" : "=r"(r) : "r"(v)); return r;
}
__device__ __forceinline__ unsigned redux_max_u32(unsigned v) {
    unsigned r; asm("redux.sync.max.u32 %0, %1, 0xffffffff;" : "=r"(r) : "r"(v)); return r;
}
// monotone float <-> u32 key
__device__ __forceinline__ unsigned f2key(float f) {
    unsigned b = __float_as_uint(f);
    return (b & 0x80000000u) ? ~b : (b | 0x80000000u);
}
__device__ __forceinline__ float key2f(unsigned k) {
    unsigned b = (k & 0x80000000u) ? (k & 0x7FFFFFFFu) : ~k;
    return __uint_as_float(b);
}
__device__ __forceinline__ float warp_sum(float v) {
    #pragma unroll
    for (int o = 16; o > 0; o >>= 1)
        v += __shfl_down_sync(0xFFFFFFFFu, v, o);
    return v;
}
// fetch-add with acq_rel gpu scope: orders this CTA's prior global writes
// (release) and makes all earlier CTAs' writes visible to the winner (acquire).
__device__ __forceinline__ unsigned atom_inc_acqrel(unsigned* p) {
    unsigned old;
    asm volatile("atom.acq_rel.gpu.global.add.u32 %0, [%1], 1;"
                 : "=r"(old) : "l"(p) : "memory");
    return old;
}

__global__ __launch_bounds__(TPB, 1) void ndcg_kernel(
    const float* __restrict__ preds,
    const float* __restrict__ target,
    float* __restrict__ out)
{
    __shared__ __align__(16) float sn[LEN];        // negated preds row
    __shared__ float spart[SUBS][M + 1];           // grid partials (padded)
    __shared__ float sg[M];                        // grid f values
    __shared__ float sred[64];
    __shared__ unsigned skey[64];                  // min/max keys
    __shared__ float s_lo, s_hi;
    __shared__ int   scnt[5];
    __shared__ int   slast;

    const int b    = blockIdx.x;
    const int tid  = threadIdx.x;
    const int lane = tid & 31;
    const int warp = tid >> 5;

    const float pi = preds[b * LEN + tid];
    const float ti = target[b * LEN + tid];
    sn[tid] = -pi;
    if (tid < 5) scnt[tid] = 0;
    if (tid == 0) slast = 0;

    // ---- row min/max via integer redux on monotone keys ----
    const unsigned key = f2key(pi);
    const unsigned wmn = redux_min_u32(key);
    const unsigned wmx = redux_max_u32(key);
    if (lane == 0) { skey[warp] = wmn; skey[32 + warp] = wmx; }
    __syncthreads();   // sn staged, scnt zeroed, keys in skey

    // ---- grade counting via warp ballots (grade 0 count unused) ----
    const int gi = (int)ti;
    #pragma unroll
    for (int gr = 1; gr < 5; ++gr) {
        unsigned bl = __ballot_sync(0xFFFFFFFFu, gi == gr);
        if (lane == 0) atomicAdd(&scnt[gr], __popc(bl));
    }
    if (warp == 0) {
        const unsigned a = redux_min_u32(skey[lane]);
        const unsigned c = redux_max_u32(skey[32 + lane]);
        if (lane == 0) { s_lo = key2f(a); s_hi = key2f(c); }
    }
    __syncthreads();

    const float lo   = s_lo;
    const float span = fmaxf(s_hi - lo, 1e-3f);
    const float h    = span / (float)(M - 4);
    const float invh = (float)(M - 4) / span;

    // ---- build f on the grid: point m_pt, j-chunk sub ----
    const int m_pt = tid & (M - 1);
    const int sub  = tid >> 4;                     // 0..63
    const float x  = lo + ((float)m_pt - 1.5f) * h;

    const float A = 0.5641896f;
    const float B = 0.0126140f;
    const ull x2 = pack2(x, x);
    const ull A2 = pack2(A, A);
    const ull B2 = pack2(B, B);
    const ull* sn2 = reinterpret_cast<const ull*>(sn);

    float s0 = 0.0f, s1 = 0.0f;
    const int base = sub * (M / 2);                // 8 x f32x2 = 16 elems
    #pragma unroll
    for (int jj = 0; jj < M / 2; ++jj) {
        ull v  = sn2[base + jj];                   // LDS.64 (2 bcast groups, no conflict)
        ull d  = add2(x2, v);                      // x - p_j (pairwise)
        ull dd = mul2(d, d);
        ull u  = fma2(dd, B2, A2);
        ull t  = mul2(d, u);
        float t0, t1; unpack2(t, t0, t1);
        s0 += tanh_fast(t0);
        s1 += tanh_fast(t1);
    }
    spart[sub][m_pt] = s0 + s1;
    __syncthreads();

    // ---- parallel grid reduce: warp w (w<16) reduces point w ----
    if (warp < M) {
        float g = spart[lane][warp] + spart[lane + 32][warp];  // padded: conflict-free
        g = warp_sum(g);
        if (lane == 0) sg[warp] = g;
    }
    __syncthreads();

    // ---- cubic Lagrange interpolation of f at p_i ----
    const float u  = (pi - lo) * invh + 1.5f;
    int m = (int)floorf(u);
    m = min(max(m, 1), M - 3);
    const float tf = u - (float)m;
    const float ta = tf - 1.0f;
    const float tb = tf - 2.0f;
    const float tc = tf + 1.0f;
    const float wm1 = -tf * ta * tb * (1.0f / 6.0f);
    const float w0  =  tc * ta * tb * 0.5f;
    const float w1  = -tc * tf * tb * 0.5f;
    const float w2  =  tc * tf * ta * (1.0f / 6.0f);
    const float f = wm1 * sg[m - 1] + w0 * sg[m] + w1 * sg[m + 1] + w2 * sg[m + 2];

    const float er   = 512.5f + 0.5f * f;          // 1 + (L-1)/2 + 0.5*f
    const float gain = (float)((1 << gi) - 1);     // grades are integer 0..4
    float dcg_i = __fdividef(gain, __log2f(er + 1.0f));

    // ---- ideal DCG term at descending rank tid ----
    const int c4 = scnt[4];
    const int c3 = c4 + scnt[3];
    const int c2 = c3 + scnt[2];
    const int c1 = c2 + scnt[1];
    const int gr = (tid < c4) ? 4 : (tid < c3) ? 3 : (tid < c2) ? 2 : (tid < c1) ? 1 : 0;
    float idcg_i = __fdividef((float)((1 << gr) - 1), __log2f((float)(tid + 2)));

    // ---- block reduction (dcg, idcg together) ----
    #pragma unroll
    for (int o = 16; o > 0; o >>= 1) {
        dcg_i  += __shfl_down_sync(0xFFFFFFFFu, dcg_i,  o);
        idcg_i += __shfl_down_sync(0xFFFFFFFFu, idcg_i, o);
    }
    __syncthreads();   // sred reuse safe
    if (lane == 0) { sred[warp] = dcg_i; sred[32 + warp] = idcg_i; }
    __syncthreads();

    if (warp == 0) {
        float d  = sred[lane];
        float id = sred[32 + lane];
        #pragma unroll
        for (int o = 16; o > 0; o >>= 1) {
            d  += __shfl_down_sync(0xFFFFFFFFu, d,  o);
            id += __shfl_down_sync(0xFFFFFFFFu, id, o);
        }
        if (lane == 0) {
            g_ndcg[b] = d / (id + 1e-10f);
            unsigned old = atom_inc_acqrel(&g_done);   // release g_ndcg write
            slast = (old == (unsigned)(gridDim.x - 1));
        }
    }
    __syncthreads();

    // ---- fused finalize: last CTA computes the mean ----
    if (slast) {
        if (tid < BATCH) {
            float v = warp_sum(g_ndcg[tid]);
            if (lane == 0) sred[warp] = v;
        }
        __syncthreads();
        if (tid == 0) {
            float s = sred[0] + sred[1] + sred[2] + sred[3];
            out[0] = -s / (float)BATCH;
            g_done = 0;                 // reset for next graph replay
        }
    }
}

extern "C" void kernel_launch(void* const* d_in, const int* in_sizes, int n_in,
                              void* d_out, int out_size)
{
    const float* preds  = (const float*)d_in[0];
    const float* target = (const float*)d_in[1];
    float* out = (float*)d_out;

    ndcg_kernel<<<BATCH, TPB>>>(preds, target, out);
}

// round 9
// speedup vs baseline: 1.2657x; 1.0037x over previous
#include <cuda_runtime.h>
#include <cuda_bf16.h>

// SoftRankNDCGLoss: B=128, L=1024
//
// s_i = f(p_i), f(x) = sum_j erf((x - p_j)/2)  (Gaussian-smoothed ECDF).
// Build f on an adaptive M=16 grid per row (tanh-cubic erf approx, HW tanh,
// packed f32x2), cubic-interpolate f at each p_i.
// er_i = 512.5 + 0.5*f(p_i); dcg = sum (2^t-1)/log2(er+1); idcg via counting
// sort. Per-row ndcg accumulated with a global float atomic; the last CTA's
// leader writes -acc/B (acq_rel counter, no threadfence, no block finalize).

constexpr int BATCH = 128;
constexpr int LEN   = 1024;
constexpr int M     = 16;               // grid points per row
constexpr int SUBS  = LEN / M;          // 64 j-chunks
constexpr int TPB   = 1024;

__device__ float    g_acc  = 0.0f;
__device__ unsigned g_done = 0;

typedef unsigned long long ull;

__device__ __forceinline__ ull pack2(float lo, float hi) {
    ull r; asm("mov.b64 %0, {%1, %2};" : "=l"(r) : "f"(lo), "f"(hi)); return r;
}
__device__ __forceinline__ void unpack2(ull v, float& lo, float& hi) {
    asm("mov.b64 {%0, %1}, %2;" : "=f"(lo), "=f"(hi) : "l"(v));
}
__device__ __forceinline__ ull add2(ull a, ull b) {
    ull r; asm("add.rn.f32x2 %0, %1, %2;" : "=l"(r) : "l"(a), "l"(b)); return r;
}
__device__ __forceinline__ ull mul2(ull a, ull b) {
    ull r; asm("mul.rn.f32x2 %0, %1, %2;" : "=l"(r) : "l"(a), "l"(b)); return r;
}
__device__ __forceinline__ ull fma2(ull a, ull b, ull c) {
    ull r; asm("fma.rn.f32x2 %0, %1, %2, %3;" : "=l"(r) : "l"(a), "l"(b), "l"(c)); return r;
}
__device__ __forceinline__ float tanh_fast(float x) {
    float r; asm("tanh.approx.f32 %0, %1;" : "=f"(r) : "f"(x)); return r;
}
// integer warp redux (supported on sm_103; f32 redux is NOT)
__device__ __forceinline__ unsigned redux_min_u32(unsigned v) {
    unsigned r; asm("redux.sync.min.u32 %0, %1, 0xffffffff;" : "=r"(r) : "r"(v)); return r;
}
__device__ __forceinline__ unsigned redux_max_u32(unsigned v) {
    unsigned r; asm("redux.sync.max.u32 %0, %1, 0xffffffff;" : "=r"(r) : "r"(v)); return r;
}
// monotone float <-> u32 key
__device__ __forceinline__ unsigned f2key(float f) {
    unsigned b = __float_as_uint(f);
    return (b & 0x80000000u) ? ~b : (b | 0x80000000u);
}
__device__ __forceinline__ float key2f(unsigned k) {
    unsigned b = (k & 0x80000000u) ? (k & 0x7FFFFFFFu) : ~k;
    return __uint_as_float(b);
}
__device__ __forceinline__ float warp_sum(float v) {
    #pragma unroll
    for (int o = 16; o > 0; o >>= 1)
        v += __shfl_down_sync(0xFFFFFFFFu, v, o);
    return v;
}
// fetch-add with acq_rel gpu scope: releases this CTA's prior global writes,
// and (for the winner) acquires all earlier CTAs' released writes.
__device__ __forceinline__ unsigned atom_inc_acqrel(unsigned* p) {
    unsigned old;
    asm volatile("atom.acq_rel.gpu.global.add.u32 %0, [%1], 1;"
                 : "=r"(old) : "l"(p) : "memory");
    return old;
}

__global__ __launch_bounds__(TPB, 1) void ndcg_kernel(
    const float* __restrict__ preds,
    const float* __restrict__ target,
    float* __restrict__ out)
{
    __shared__ __align__(16) float sn[LEN];        // negated preds row
    __shared__ float spart[SUBS][M + 1];           // grid partials (padded)
    __shared__ float sg[M];                        // grid f values
    __shared__ float sred[64];                     // dcg/idcg partials
    __shared__ unsigned skey[64];                  // min/max keys
    __shared__ int   scnt[5];

    const int b    = blockIdx.x;
    const int tid  = threadIdx.x;
    const int lane = tid & 31;
    const int warp = tid >> 5;

    const float pi = preds[b * LEN + tid];
    const float ti = target[b * LEN + tid];
    sn[tid] = -pi;
    if (tid < 5) scnt[tid] = 0;

    // ---- per-warp min/max keys ----
    const unsigned key = f2key(pi);
    const unsigned wmn = redux_min_u32(key);
    const unsigned wmx = redux_max_u32(key);
    if (lane == 0) { skey[warp] = wmn; skey[32 + warp] = wmx; }
    __syncthreads();   // sn staged, scnt zeroed, keys in skey

    // ---- grade counting via warp ballots (grade 0 count unused) ----
    const int gi = (int)ti;
    #pragma unroll
    for (int gr = 1; gr < 5; ++gr) {
        unsigned bl = __ballot_sync(0xFFFFFFFFu, gi == gr);
        if (lane == 0) atomicAdd(&scnt[gr], __popc(bl));
    }

    // ---- all warps redundantly finish min/max (no extra barrier) ----
    const float lo   = key2f(redux_min_u32(skey[lane]));
    const float hi   = key2f(redux_max_u32(skey[32 + lane]));
    const float span = fmaxf(hi - lo, 1e-3f);
    const float h    = span / (float)(M - 4);
    const float invh = (float)(M - 4) / span;

    // ---- build f on the grid: point m_pt, j-chunk sub ----
    const int m_pt = tid & (M - 1);
    const int sub  = tid >> 4;                     // 0..63
    const float x  = lo + ((float)m_pt - 1.5f) * h;

    const float A = 0.5641896f;
    const float B = 0.0126140f;
    const ull x2 = pack2(x, x);
    const ull A2 = pack2(A, A);
    const ull B2 = pack2(B, B);
    const ull* sn2 = reinterpret_cast<const ull*>(sn);

    float s0 = 0.0f, s1 = 0.0f;
    const int base = sub * (M / 2);                // 8 x f32x2 = 16 elems
    #pragma unroll
    for (int jj = 0; jj < M / 2; ++jj) {
        ull v  = sn2[base + jj];
        ull d  = add2(x2, v);                      // x - p_j (pairwise)
        ull dd = mul2(d, d);
        ull u  = fma2(dd, B2, A2);
        ull t  = mul2(d, u);
        float t0, t1; unpack2(t, t0, t1);
        s0 += tanh_fast(t0);
        s1 += tanh_fast(t1);
    }
    spart[sub][m_pt] = s0 + s1;
    __syncthreads();

    // ---- parallel grid reduce: warp w (w<16) reduces point w ----
    if (warp < M) {
        float g = spart[lane][warp] + spart[lane + 32][warp];  // padded: conflict-free
        g = warp_sum(g);
        if (lane == 0) sg[warp] = g;
    }
    __syncthreads();

    // ---- cubic Lagrange interpolation of f at p_i ----
    const float u  = (pi - lo) * invh + 1.5f;
    int m = (int)floorf(u);
    m = min(max(m, 1), M - 3);
    const float tf = u - (float)m;
    const float ta = tf - 1.0f;
    const float tb = tf - 2.0f;
    const float tc = tf + 1.0f;
    const float wm1 = -tf * ta * tb * (1.0f / 6.0f);
    const float w0  =  tc * ta * tb * 0.5f;
    const float w1  = -tc * tf * tb * 0.5f;
    const float w2  =  tc * tf * ta * (1.0f / 6.0f);
    const float f = wm1 * sg[m - 1] + w0 * sg[m] + w1 * sg[m + 1] + w2 * sg[m + 2];

    const float er   = 512.5f + 0.5f * f;          // 1 + (L-1)/2 + 0.5*f
    const float gain = (float)((1 << gi) - 1);     // grades are integer 0..4
    float dcg_i = __fdividef(gain, __log2f(er + 1.0f));

    // ---- ideal DCG term at descending rank tid ----
    const int c4 = scnt[4];
    const int c3 = c4 + scnt[3];
    const int c2 = c3 + scnt[2];
    const int c1 = c2 + scnt[1];
    const int gr = (tid < c4) ? 4 : (tid < c3) ? 3 : (tid < c2) ? 2 : (tid < c1) ? 1 : 0;
    float idcg_i = __fdividef((float)((1 << gr) - 1), __log2f((float)(tid + 2)));

    // ---- block reduction (dcg, idcg together) ----
    #pragma unroll
    for (int o = 16; o > 0; o >>= 1) {
        dcg_i  += __shfl_down_sync(0xFFFFFFFFu, dcg_i,  o);
        idcg_i += __shfl_down_sync(0xFFFFFFFFu, idcg_i, o);
    }
    if (lane == 0) { sred[warp] = dcg_i; sred[32 + warp] = idcg_i; }
    __syncthreads();

    if (warp == 0) {
        float d  = sred[lane];
        float id = sred[32 + lane];
        #pragma unroll
        for (int o = 16; o > 0; o >>= 1) {
            d  += __shfl_down_sync(0xFFFFFFFFu, d,  o);
            id += __shfl_down_sync(0xFFFFFFFFu, id, o);
        }
        if (lane == 0) {
            const float ndcg_b = d / (id + 1e-10f);
            atomicAdd(&g_acc, ndcg_b);
            unsigned old = atom_inc_acqrel(&g_done);   // release the add
            if (old == (unsigned)(gridDim.x - 1)) {
                // winner: all 128 adds are visible (acquire)
                float acc = *((volatile float*)&g_acc);
                out[0] = -acc / (float)BATCH;
                g_acc  = 0.0f;          // reset for next graph replay
                g_done = 0u;
            }
        }
    }
}

extern "C" void kernel_launch(void* const* d_in, const int* in_sizes, int n_in,
                              void* d_out, int out_size)
{
    const float* preds  = (const float*)d_in[0];
    const float* target = (const float*)d_in[1];
    float* out = (float*)d_out;

    ndcg_kernel<<<BATCH, TPB>>>(preds, target, out);
}